// round 9
// baseline (speedup 1.0000x reference)
#include <cuda_runtime.h>
#include <math.h>

#define T 96
#define B 1024
#define K 10
#define C 16
#define H 32
#define G 256
#define L 4
#define KH (K*H)     // 320
#define E4 4         // batch elements per GNN block
#define NBP 16       // batches per projection block
#define GB 8         // batches per recurrent block

typedef unsigned long long ull;
typedef unsigned int uint;

__device__ float g_comb[(size_t)T * KH * B];     // [t][kh][b]
__device__ float g_proj[(size_t)T * 3 * B * G];  // [t][s][b][g]  (transposed!)
__device__ float g_h[B * G];
__device__ float g_wcatT[3 * G * KH];            // [(s*G+j)][i]
__device__ float g_bcat[3 * G];
// packed gnn gate weights (built by prep_kernel)
__device__ ulonglong2 g_wzr[L*H*H];              // {{wz,uz},{wr,ur}}
__device__ ull        g_wh0[L*H*H];              // {wh, 0}
__device__ ull        g_uh2[L*H*H];              // {uh, uh}
// interleaved recur weights
__device__ float2     g_uzr[G*G];                // {uz, ur} at [i*G+g]

__device__ __forceinline__ float fast_tanh(float x) {
    float y; asm("tanh.approx.f32 %0, %1;" : "=f"(y) : "f"(x)); return y;
}
__device__ __forceinline__ float fast_sigmoid(float x) {
    return fmaf(0.5f, fast_tanh(0.5f * x), 0.5f);
}
__device__ __forceinline__ ull pack2(float a, float b) {
    ull r; asm("mov.b64 %0,{%1,%2};" : "=l"(r) : "f"(a), "f"(b)); return r;
}
__device__ __forceinline__ ull pack1(float a) { return pack2(a, a); }
__device__ __forceinline__ void unpack2(ull v, float& a, float& b) {
    asm("mov.b64 {%0,%1},%2;" : "=f"(a), "=f"(b) : "l"(v));
}
__device__ __forceinline__ ull fma2(ull a, ull b, ull c) {
    ull d; asm("fma.rn.f32x2 %0,%1,%2,%3;" : "=l"(d) : "l"(a), "l"(b), "l"(c)); return d;
}
__device__ __forceinline__ ull add2(ull a, ull b) {
    ull d; asm("add.rn.f32x2 %0,%1,%2;" : "=l"(d) : "l"(a), "l"(b)); return d;
}
__device__ __forceinline__ ull shfl_xor_ull(ull v, int m) {
    uint lo = (uint)v, hi = (uint)(v >> 32);
    lo = __shfl_xor_sync(0xffffffffu, lo, m);
    hi = __shfl_xor_sync(0xffffffffu, hi, m);
    return ((ull)hi << 32) | (ull)lo;
}
// 4 lanes (quarters) each hold partials a[0..3] (batch-pairs). After: this
// lane (quarter q, bits b,c) holds the full sum for batch-pair q.
__device__ __forceinline__ ull quad_reduce(const ull a[4], int b, int c) {
    ull k0 = b ? a[1] : a[0], g0 = b ? a[0] : a[1];
    ull k1 = b ? a[3] : a[2], g1 = b ? a[2] : a[3];
    ull s0 = add2(k0, shfl_xor_ull(g0, 1));
    ull s1 = add2(k1, shfl_xor_ull(g1, 1));
    ull k2 = c ? s1 : s0, g2 = c ? s0 : s1;
    return add2(k2, shfl_xor_ull(g2, 2));
}

// ---------------------------------------------------------------------------
// prep: pack gnn gate weights and interleave recur z/r weights.
// grid: 256 blocks x 256 threads = 65536 = G*G.
// ---------------------------------------------------------------------------
__global__ __launch_bounds__(256) void prep_kernel(
    const float* __restrict__ Wz, const float* __restrict__ Uz,
    const float* __restrict__ Wr, const float* __restrict__ Ur,
    const float* __restrict__ Wh, const float* __restrict__ Uh,
    const float* __restrict__ Ugz, const float* __restrict__ Ugr)
{
    int idx = blockIdx.x * blockDim.x + threadIdx.x;
    if (idx < L*H*H) {
        g_wzr[idx] = make_ulonglong2(pack2(Wz[idx], Uz[idx]), pack2(Wr[idx], Ur[idx]));
        g_wh0[idx] = pack2(Wh[idx], 0.f);
        g_uh2[idx] = pack1(Uh[idx]);
    }
    g_uzr[idx] = make_float2(Ugz[idx], Ugr[idx]);
}

// ---------------------------------------------------------------------------
// Weight combine (unchanged)
// ---------------------------------------------------------------------------
__global__ __launch_bounds__(G) void wcomb_kernel(
    const float* __restrict__ Wgp, const float* __restrict__ bgp,
    const float* __restrict__ Wgz, const float* __restrict__ bgz,
    const float* __restrict__ Wgr, const float* __restrict__ bgr,
    const float* __restrict__ Wgn, const float* __restrict__ bgn)
{
    __shared__ float sa[G], sb[G];
    const int i = blockIdx.x, s = blockIdx.y, j = threadIdx.x;
    const float* Ws = (s == 0) ? Wgz : (s == 1) ? Wgr : Wgn;
    const float* bs = (s == 0) ? bgz : (s == 1) ? bgr : bgn;

    sa[j] = Wgp[i*G + j];
    if (i == 0) sb[j] = bgp[j];
    __syncthreads();

    float acc = 0.f;
    #pragma unroll 8
    for (int k = 0; k < G; k++) acc += sa[k] * Ws[k*G + j];
    g_wcatT[(s*G + j)*KH + i] = acc;

    if (i == 0) {
        float bacc = bs[j];
        #pragma unroll 8
        for (int k = 0; k < G; k++) bacc += sb[k] * Ws[k*G + j];
        g_bcat[s*G + j] = bacc;
    }
}

// ---------------------------------------------------------------------------
// GNN: grid (B/E4, T), 320 threads = (k,j). Packed weights from prep.
// ---------------------------------------------------------------------------
__global__ __launch_bounds__(KH, 3) void gnn_kernel(
    const float* __restrict__ x, const float* __restrict__ adj,
    const float* __restrict__ W_fi, const float* __restrict__ b_fi,
    const float* __restrict__ bz, const float* __restrict__ br,
    const float* __restrict__ bh)
{
    __shared__ float      sx[E4][K*C];
    __shared__ float      sadj[E4][K*K];
    __shared__ float      sdeg[E4][K];
    __shared__ ulonglong2 sadjT[K*K];
    __shared__ float4     sh4[KH], sh04[KH];
    __shared__ ull        smh[KH][4];     // {m_e, h_e} packed per batch e
    __shared__ ull        ssrh[KH][2];    // {rh0,rh1},{rh2,rh3}

    const int b0  = blockIdx.x * E4;
    const int t   = blockIdx.y;
    const int tid = threadIdx.x;
    const int k   = tid >> 5;
    const int j   = tid & 31;

    for (int idx = tid; idx < E4*K*C; idx += KH) {
        int e = idx / (K*C), r = idx - e*(K*C);
        sx[e][r] = x[((size_t)t*B + b0 + e)*(K*C) + r];
    }
    for (int idx = tid; idx < E4*K*K; idx += KH) {
        int e = idx / (K*K), r = idx - e*(K*K);
        int row = r / K, col = r - row*K;
        sadj[e][r] = adj[((size_t)t*B + b0 + e)*(K*K) + r] + (row == col ? 1.f : 0.f);
    }
    __syncthreads();
    if (tid < E4*K) {
        int e = tid / K, r = tid - e*K;
        float s = 0.f;
        #pragma unroll
        for (int i = 0; i < K; i++) s += sadj[e][r*K + i];
        sdeg[e][r] = 1.f / (s + 1e-6f);
    }
    __syncthreads();
    for (int idx = tid; idx < E4*K*K; idx += KH) {
        int e = idx / (K*K), r = idx - e*(K*K);
        sadj[e][r] *= sdeg[e][r / K];
    }
    __syncthreads();
    if (tid < K*K) {
        sadjT[tid] = make_ulonglong2(pack2(sadj[0][tid], sadj[1][tid]),
                                     pack2(sadj[2][tid], sadj[3][tid]));
    }

    // h0 = x @ W_fi + b_fi
    float a0[E4];
    {
        float bv = b_fi[j];
        #pragma unroll
        for (int e = 0; e < E4; e++) a0[e] = bv;
    }
    #pragma unroll
    for (int c = 0; c < C; c++) {
        float w = W_fi[c*H + j];
        #pragma unroll
        for (int e = 0; e < E4; e++) a0[e] += sx[e][k*C + c] * w;
    }
    {
        float4 v = make_float4(a0[0], a0[1], a0[2], a0[3]);
        sh04[tid] = v;
        sh4[tid]  = v;
    }
    __syncthreads();

    for (int l = 0; l < L; l++) {
        // m = adj_norm @ h
        ull mp01 = 0ULL, mp23 = 0ULL;
        #pragma unroll
        for (int i = 0; i < K; i++) {
            ulonglong2 a2 = sadjT[k*K + i];
            ulonglong2 h2 = *(const ulonglong2*)&sh4[i*H + j];
            mp01 = fma2(a2.x, h2.x, mp01);
            mp23 = fma2(a2.y, h2.y, mp23);
        }
        float4 hown = sh4[tid];
        {
            float m0, m1, m2, m3;
            unpack2(mp01, m0, m1); unpack2(mp23, m2, m3);
            *(ulonglong2*)&smh[tid][0] =
                make_ulonglong2(pack2(m0, hown.x), pack2(m1, hown.y));
            *(ulonglong2*)&smh[tid][2] =
                make_ulonglong2(pack2(m2, hown.z), pack2(m3, hown.w));
        }
        __syncthreads();

        // gates via packed weights: 2 LDG + 2 LDS + 12 FMA2 per iter
        ull azp[E4] = {0,0,0,0}, arp[E4] = {0,0,0,0}, anp[E4] = {0,0,0,0};
        #pragma unroll 4
        for (int i = 0; i < H; i++) {
            ulonglong2 wzr = g_wzr[(l*H + i)*H + j];
            ull        wh0 = g_wh0[(l*H + i)*H + j];
            ulonglong2 c01 = *(const ulonglong2*)&smh[k*H + i][0];
            ulonglong2 c23 = *(const ulonglong2*)&smh[k*H + i][2];
            azp[0] = fma2(c01.x, wzr.x, azp[0]);  azp[1] = fma2(c01.y, wzr.x, azp[1]);
            azp[2] = fma2(c23.x, wzr.x, azp[2]);  azp[3] = fma2(c23.y, wzr.x, azp[3]);
            arp[0] = fma2(c01.x, wzr.y, arp[0]);  arp[1] = fma2(c01.y, wzr.y, arp[1]);
            arp[2] = fma2(c23.x, wzr.y, arp[2]);  arp[3] = fma2(c23.y, wzr.y, arp[3]);
            anp[0] = fma2(c01.x, wh0, anp[0]);    anp[1] = fma2(c01.y, wh0, anp[1]);
            anp[2] = fma2(c23.x, wh0, anp[2]);    anp[3] = fma2(c23.y, wh0, anp[3]);
        }
        float zg[E4], rg[E4], anf[E4];
        {
            float bzv = bz[l*H + j], brv = br[l*H + j], bnv = bh[l*H + j];
            #pragma unroll
            for (int e = 0; e < E4; e++) {
                float a, b;
                unpack2(azp[e], a, b);  zg[e] = fast_sigmoid(a + b + bzv);
                unpack2(arp[e], a, b);  rg[e] = fast_sigmoid(a + b + brv);
                unpack2(anp[e], a, b);  anf[e] = a + b + bnv;
            }
        }
        *(ulonglong2*)&ssrh[tid][0] =
            make_ulonglong2(pack2(rg[0]*hown.x, rg[1]*hown.y),
                            pack2(rg[2]*hown.z, rg[3]*hown.w));
        __syncthreads();   // ssrh published; all sh4/smh reads of this layer done

        // n remainder: (r*h) @ Uh, packed pairs
        ull an01 = pack2(anf[0], anf[1]);
        ull an23 = pack2(anf[2], anf[3]);
        #pragma unroll 4
        for (int i = 0; i < H; i++) {
            ull uh2 = g_uh2[(l*H + i)*H + j];
            ulonglong2 rv = *(const ulonglong2*)&ssrh[k*H + i][0];
            an01 = fma2(rv.x, uh2, an01);
            an23 = fma2(rv.y, uh2, an23);
        }
        unpack2(an01, anf[0], anf[1]);
        unpack2(an23, anf[2], anf[3]);
        float4 h0v = sh04[tid];
        float4 hn;
        hn.x = (1.f - zg[0])*hown.x + zg[0]*fast_tanh(anf[0]) + h0v.x;
        hn.y = (1.f - zg[1])*hown.y + zg[1]*fast_tanh(anf[1]) + h0v.y;
        hn.z = (1.f - zg[2])*hown.z + zg[2]*fast_tanh(anf[2]) + h0v.z;
        hn.w = (1.f - zg[3])*hown.w + zg[3]*fast_tanh(anf[3]) + h0v.w;
        sh4[tid] = hn;     // safe: all reads of sh4 completed before ssrh barrier
        __syncthreads();
    }

    *(float4*)&g_comb[((size_t)t*KH + tid)*B + b0] = sh4[tid];
}

// ---------------------------------------------------------------------------
// Projection: g_proj[t][s][b][g] = comb[t][:,b] @ WcatT[s*G+g][:] + bcat
// grid (B/NBP, T), 256 threads. Coalesced [b][g] stores.
// ---------------------------------------------------------------------------
__global__ __launch_bounds__(G, 2) void proj_kernel()
{
    __shared__ ulonglong2 scomb[KH][NBP/4];   // 20KB

    const int g  = threadIdx.x;
    const int b0 = blockIdx.x * NBP;
    const int t  = blockIdx.y;

    for (int idx = g; idx < KH*(NBP/4); idx += G) {
        int row = idx >> 2, p = idx & 3;
        scomb[row][p] = *(const ulonglong2*)&g_comb[((size_t)t*KH + row)*B + b0 + 4*p];
    }
    __syncthreads();

    ull acc[3][8];
    #pragma unroll
    for (int s = 0; s < 3; s++) {
        ull bv = pack1(g_bcat[s*G + g]);
        #pragma unroll
        for (int q = 0; q < 8; q++) acc[s][q] = bv;
    }
    const float* w0 = g_wcatT + (0*G + g)*KH;
    const float* w1 = g_wcatT + (1*G + g)*KH;
    const float* w2 = g_wcatT + (2*G + g)*KH;

    #pragma unroll 2
    for (int i = 0; i < KH; i += 4) {
        float4 wa = *(const float4*)(w0 + i);
        float4 wb = *(const float4*)(w1 + i);
        float4 wc = *(const float4*)(w2 + i);
        #pragma unroll
        for (int u = 0; u < 4; u++) {
            float wav = (u==0)?wa.x:(u==1)?wa.y:(u==2)?wa.z:wa.w;
            float wbv = (u==0)?wb.x:(u==1)?wb.y:(u==2)?wb.z:wb.w;
            float wcv = (u==0)?wc.x:(u==1)?wc.y:(u==2)?wc.z:wc.w;
            ull wa2 = pack1(wav), wb2 = pack1(wbv), wc2 = pack1(wcv);
            #pragma unroll
            for (int p = 0; p < 4; p++) {
                ulonglong2 c = scomb[i + u][p];
                acc[0][2*p]   = fma2(c.x, wa2, acc[0][2*p]);
                acc[0][2*p+1] = fma2(c.y, wa2, acc[0][2*p+1]);
                acc[1][2*p]   = fma2(c.x, wb2, acc[1][2*p]);
                acc[1][2*p+1] = fma2(c.y, wb2, acc[1][2*p+1]);
                acc[2][2*p]   = fma2(c.x, wc2, acc[2][2*p]);
                acc[2][2*p+1] = fma2(c.y, wc2, acc[2][2*p+1]);
            }
        }
    }
    // store transposed: [t][s][b][g], fully coalesced (g contiguous)
    #pragma unroll
    for (int s = 0; s < 3; s++) {
        float* dst = &g_proj[(((size_t)t*3 + s)*B + b0)*G + g];
        #pragma unroll
        for (int q = 0; q < 8; q++) {
            float lo, hi;
            unpack2(acc[s][q], lo, hi);
            dst[(size_t)(2*q)*G]     = lo;
            dst[(size_t)(2*q+1)*G]   = hi;
        }
    }
}

// ---------------------------------------------------------------------------
// Recurrent GARU: 128 blocks x 1024 threads. tid = g*4 + q.
// Quarter q covers rows i ≡ q (mod 4). Cross-quarter reduction via shfl;
// h register-resident (batch-pair q of column g).
// ---------------------------------------------------------------------------
__global__ __launch_bounds__(1024, 1) void recur_kernel(
    const float* __restrict__ Ugn)
{
    __shared__ ull sh[G][4];    // [col][batch-pair]
    __shared__ ull srh[G][4];

    const int tid = threadIdx.x;
    const int g   = tid >> 2;
    const int q   = tid & 3;
    const int bsel = q & 1;
    const int csel = (q >> 1) & 1;
    const int b0  = blockIdx.x * GB;

    ull hreg = 0ULL;
    sh[g][q] = 0ULL;
    __syncthreads();

    for (int t = 0; t < T; t++) {
        // pass 1: partial h@Ugz, h@Ugr over rows i ≡ q (mod 4)
        ull az[4] = {0,0,0,0}, ar[4] = {0,0,0,0};
        #pragma unroll 4
        for (int i = q; i < G; i += 4) {
            float2 w = g_uzr[i*G + g];
            ull uz2 = pack1(w.x), ur2 = pack1(w.y);
            ulonglong2 h01 = *(const ulonglong2*)&sh[i][0];
            ulonglong2 h23 = *(const ulonglong2*)&sh[i][2];
            az[0] = fma2(h01.x, uz2, az[0]);  az[1] = fma2(h01.y, uz2, az[1]);
            az[2] = fma2(h23.x, uz2, az[2]);  az[3] = fma2(h23.y, uz2, az[3]);
            ar[0] = fma2(h01.x, ur2, ar[0]);  ar[1] = fma2(h01.y, ur2, ar[1]);
            ar[2] = fma2(h23.x, ur2, ar[2]);  ar[3] = fma2(h23.y, ur2, ar[3]);
        }
        ull azf = quad_reduce(az, bsel, csel);
        ull arf = quad_reduce(ar, bsel, csel);

        // add projected gate inputs ([t][s][b][g], b = b0 + 2q + {0,1})
        const size_t pz = (((size_t)t*3 + 0)*B + b0 + 2*q)*G + g;
        azf = add2(azf, pack2(g_proj[pz],              g_proj[pz + G]));
        const size_t pr = pz + (size_t)B*G;
        arf = add2(arf, pack2(g_proj[pr],              g_proj[pr + G]));
        const size_t pnI = pz + (size_t)2*B*G;
        ull pn = pack2(g_proj[pnI], g_proj[pnI + G]);

        float z0, z1, r0, r1, h0, h1;
        unpack2(azf, z0, z1);  unpack2(arf, r0, r1);  unpack2(hreg, h0, h1);
        z0 = fast_sigmoid(z0);  z1 = fast_sigmoid(z1);
        r0 = fast_sigmoid(r0) * h0;
        r1 = fast_sigmoid(r1) * h1;
        srh[g][q] = pack2(r0, r1);
        __syncthreads();

        // pass 2: partial (r*h)@Ugn
        ull an[4] = {0,0,0,0};
        #pragma unroll 4
        for (int i = q; i < G; i += 4) {
            ull un2 = pack1(Ugn[i*G + g]);
            ulonglong2 s01 = *(const ulonglong2*)&srh[i][0];
            ulonglong2 s23 = *(const ulonglong2*)&srh[i][2];
            an[0] = fma2(s01.x, un2, an[0]);  an[1] = fma2(s01.y, un2, an[1]);
            an[2] = fma2(s23.x, un2, an[2]);  an[3] = fma2(s23.y, un2, an[3]);
        }
        ull anf = quad_reduce(an, bsel, csel);
        anf = add2(anf, pn);
        float a0, a1;
        unpack2(anf, a0, a1);
        float hn0 = (1.f - z0)*fast_tanh(a0) + z0*h0;
        float hn1 = (1.f - z1)*fast_tanh(a1) + z1*h1;
        hreg = pack2(hn0, hn1);
        sh[g][q] = hreg;
        __syncthreads();
    }

    float h0, h1;
    unpack2(hreg, h0, h1);
    g_h[(size_t)(b0 + 2*q)*G + g]     = h0;
    g_h[(size_t)(b0 + 2*q + 1)*G + g] = h1;
}

// ---------------------------------------------------------------------------
// Classifier
// ---------------------------------------------------------------------------
__global__ __launch_bounds__(64) void cls_kernel(
    const float* __restrict__ W1, const float* __restrict__ b1,
    const float* __restrict__ W2, const float* __restrict__ b2,
    float* __restrict__ out)
{
    __shared__ float wsum[2];
    const int b = blockIdx.x;
    const int j = threadIdx.x;

    const float* hb = g_h + (size_t)b*G;
    float acc = b1[j];
    #pragma unroll 8
    for (int i = 0; i < G; i++) acc += hb[i] * W1[i*64 + j];
    float hid = fmaxf(acc, 0.f);
    float v = hid * W2[j];
    #pragma unroll
    for (int o = 16; o > 0; o >>= 1) v += __shfl_down_sync(0xffffffffu, v, o);
    if ((j & 31) == 0) wsum[j >> 5] = v;
    __syncthreads();
    if (j == 0) out[b] = fast_sigmoid(wsum[0] + wsum[1] + b2[0]);
}

extern "C" void kernel_launch(void* const* d_in, const int* in_sizes, int n_in,
                              void* d_out, int out_size)
{
    const float* x    = (const float*)d_in[0];
    const float* adj  = (const float*)d_in[1];
    const float* W_fi = (const float*)d_in[2];
    const float* b_fi = (const float*)d_in[3];
    const float* Wz   = (const float*)d_in[4];
    const float* Uz   = (const float*)d_in[5];
    const float* bz   = (const float*)d_in[6];
    const float* Wr   = (const float*)d_in[7];
    const float* Ur   = (const float*)d_in[8];
    const float* br   = (const float*)d_in[9];
    const float* Wh   = (const float*)d_in[10];
    const float* Uh   = (const float*)d_in[11];
    const float* bh   = (const float*)d_in[12];
    const float* Wgp  = (const float*)d_in[13];
    const float* bgp  = (const float*)d_in[14];
    const float* Wgz  = (const float*)d_in[15];
    const float* Ugz  = (const float*)d_in[16];
    const float* bgz  = (const float*)d_in[17];
    const float* Wgr  = (const float*)d_in[18];
    const float* Ugr  = (const float*)d_in[19];
    const float* bgr  = (const float*)d_in[20];
    const float* Wgn  = (const float*)d_in[21];
    const float* Ugn  = (const float*)d_in[22];
    const float* bgn  = (const float*)d_in[23];
    const float* W1   = (const float*)d_in[24];
    const float* b1   = (const float*)d_in[25];
    const float* W2   = (const float*)d_in[26];
    const float* b2   = (const float*)d_in[27];
    float* out = (float*)d_out;

    prep_kernel<<<G*G/256, 256>>>(Wz, Uz, Wr, Ur, Wh, Uh, Ugz, Ugr);
    wcomb_kernel<<<dim3(KH, 3), G>>>(Wgp, bgp, Wgz, bgz, Wgr, bgr, Wgn, bgn);
    gnn_kernel<<<dim3(B/E4, T), KH>>>(x, adj, W_fi, b_fi, bz, br, bh);
    proj_kernel<<<dim3(B/NBP, T), G>>>();
    recur_kernel<<<B/GB, 1024>>>(Ugn);
    cls_kernel<<<B, 64>>>(W1, b1, W2, b2, out);
}

// round 12
// speedup vs baseline: 1.4608x; 1.4608x over previous
#include <cuda_runtime.h>
#include <math.h>

#define T 96
#define B 1024
#define K 10
#define C 16
#define H 32
#define G 256
#define L 4
#define KH (K*H)     // 320
#define E4 4         // batch elements per GNN block
#define NBP 16       // batches per projection block
#define GB 8         // batches per recurrent block
#define RT 1024      // recurrent threads (256 cols x 4 reduction quarters)

typedef unsigned long long ull;

__device__ float g_comb[(size_t)T * KH * B];     // [t][kh][b]
__device__ float g_proj[(size_t)T * 3 * B * G];  // [t][s][b][g]  (g contiguous)
__device__ float g_h[B * G];
__device__ float g_wcat[KH * 3 * G];             // [i][s*G+j]  (coalesced over j)
__device__ float g_bcat[3 * G];
__device__ float2 g_uzr[G*G];                    // {uz, ur} at [i*G+g]

__device__ __forceinline__ float fast_tanh(float x) {
    float y; asm("tanh.approx.f32 %0, %1;" : "=f"(y) : "f"(x)); return y;
}
__device__ __forceinline__ float fast_sigmoid(float x) {
    return fmaf(0.5f, fast_tanh(0.5f * x), 0.5f);
}
__device__ __forceinline__ ull pack2(float a, float b) {
    ull r; asm("mov.b64 %0,{%1,%2};" : "=l"(r) : "f"(a), "f"(b)); return r;
}
__device__ __forceinline__ ull pack1(float a) { return pack2(a, a); }
__device__ __forceinline__ void unpack2(ull v, float& a, float& b) {
    asm("mov.b64 {%0,%1},%2;" : "=f"(a), "=f"(b) : "l"(v));
}
__device__ __forceinline__ ull fma2(ull a, ull b, ull c) {
    ull d; asm("fma.rn.f32x2 %0,%1,%2,%3;" : "=l"(d) : "l"(a), "l"(b), "l"(c)); return d;
}
__device__ __forceinline__ ull add2(ull a, ull b) {
    ull d; asm("add.rn.f32x2 %0,%1,%2;" : "=l"(d) : "l"(a), "l"(b)); return d;
}
__device__ __forceinline__ ulonglong2 add2v(ulonglong2 a, ulonglong2 b) {
    a.x = add2(a.x, b.x); a.y = add2(a.y, b.y); return a;
}

// ---------------------------------------------------------------------------
// prep: interleave recur z/r weights. 256 blocks x 256 threads.
// ---------------------------------------------------------------------------
__global__ __launch_bounds__(256) void prep_kernel(
    const float* __restrict__ Ugz, const float* __restrict__ Ugr)
{
    int idx = blockIdx.x * blockDim.x + threadIdx.x;
    g_uzr[idx] = make_float2(Ugz[idx], Ugr[idx]);
}

// ---------------------------------------------------------------------------
// Weight combine (coalesced output layout):
//   Wcat[i][s*G+j] = sum_k Wgp[i][k]*Wg_s[k][j]
// ---------------------------------------------------------------------------
__global__ __launch_bounds__(G) void wcomb_kernel(
    const float* __restrict__ Wgp, const float* __restrict__ bgp,
    const float* __restrict__ Wgz, const float* __restrict__ bgz,
    const float* __restrict__ Wgr, const float* __restrict__ bgr,
    const float* __restrict__ Wgn, const float* __restrict__ bgn)
{
    __shared__ float sa[G], sb[G];
    const int i = blockIdx.x, s = blockIdx.y, j = threadIdx.x;
    const float* Ws = (s == 0) ? Wgz : (s == 1) ? Wgr : Wgn;
    const float* bs = (s == 0) ? bgz : (s == 1) ? bgr : bgn;

    sa[j] = Wgp[i*G + j];
    if (i == 0) sb[j] = bgp[j];
    __syncthreads();

    float acc = 0.f;
    #pragma unroll 8
    for (int k = 0; k < G; k++) acc += sa[k] * Ws[k*G + j];
    g_wcat[i*(3*G) + s*G + j] = acc;

    if (i == 0) {
        float bacc = bs[j];
        #pragma unroll 8
        for (int k = 0; k < G; k++) bacc += sb[k] * Ws[k*G + j];
        g_bcat[s*G + j] = bacc;
    }
}

// ---------------------------------------------------------------------------
// GNN: grid (B/E4, T), 320 threads = (k,j). 4 batch elements per block.
// (exact R8 version — proven)
// ---------------------------------------------------------------------------
__global__ __launch_bounds__(KH, 3) void gnn_kernel(
    const float* __restrict__ x, const float* __restrict__ adj,
    const float* __restrict__ W_fi, const float* __restrict__ b_fi,
    const float* __restrict__ Wz, const float* __restrict__ Uz, const float* __restrict__ bz,
    const float* __restrict__ Wr, const float* __restrict__ Ur, const float* __restrict__ br,
    const float* __restrict__ Wh, const float* __restrict__ Uh, const float* __restrict__ bh)
{
    __shared__ float      sx[E4][K*C];
    __shared__ float      sadj[E4][K*K];
    __shared__ float      sdeg[E4][K];
    __shared__ ulonglong2 sadjT[K*K];
    __shared__ float4     sh4[KH], sh04[KH], srh4[KH];
    __shared__ ull        smh[KH][4];

    const int b0  = blockIdx.x * E4;
    const int t   = blockIdx.y;
    const int tid = threadIdx.x;
    const int k   = tid >> 5;
    const int j   = tid & 31;

    for (int idx = tid; idx < E4*K*C; idx += KH) {
        int e = idx / (K*C), r = idx - e*(K*C);
        sx[e][r] = x[((size_t)t*B + b0 + e)*(K*C) + r];
    }
    for (int idx = tid; idx < E4*K*K; idx += KH) {
        int e = idx / (K*K), r = idx - e*(K*K);
        int row = r / K, col = r - row*K;
        sadj[e][r] = adj[((size_t)t*B + b0 + e)*(K*K) + r] + (row == col ? 1.f : 0.f);
    }
    __syncthreads();
    if (tid < E4*K) {
        int e = tid / K, r = tid - e*K;
        float s = 0.f;
        #pragma unroll
        for (int i = 0; i < K; i++) s += sadj[e][r*K + i];
        sdeg[e][r] = 1.f / (s + 1e-6f);
    }
    __syncthreads();
    for (int idx = tid; idx < E4*K*K; idx += KH) {
        int e = idx / (K*K), r = idx - e*(K*K);
        sadj[e][r] *= sdeg[e][r / K];
    }
    __syncthreads();
    if (tid < K*K) {
        sadjT[tid] = make_ulonglong2(pack2(sadj[0][tid], sadj[1][tid]),
                                     pack2(sadj[2][tid], sadj[3][tid]));
    }

    float a0[E4];
    {
        float bv = b_fi[j];
        #pragma unroll
        for (int e = 0; e < E4; e++) a0[e] = bv;
    }
    #pragma unroll
    for (int c = 0; c < C; c++) {
        float w = W_fi[c*H + j];
        #pragma unroll
        for (int e = 0; e < E4; e++) a0[e] += sx[e][k*C + c] * w;
    }
    {
        float4 v = make_float4(a0[0], a0[1], a0[2], a0[3]);
        sh04[tid] = v;
        sh4[tid]  = v;
    }
    __syncthreads();

    for (int l = 0; l < L; l++) {
        const float* Wzl = Wz + l*H*H; const float* Uzl = Uz + l*H*H;
        const float* Wrl = Wr + l*H*H; const float* Url = Ur + l*H*H;
        const float* Whl = Wh + l*H*H; const float* Uhl = Uh + l*H*H;

        ull mp01 = 0ULL, mp23 = 0ULL;
        #pragma unroll
        for (int i = 0; i < K; i++) {
            ulonglong2 a2 = sadjT[k*K + i];
            ulonglong2 h2 = *(const ulonglong2*)&sh4[i*H + j];
            mp01 = fma2(a2.x, h2.x, mp01);
            mp23 = fma2(a2.y, h2.y, mp23);
        }
        float4 hown = sh4[tid];
        {
            float m0, m1, m2, m3;
            unpack2(mp01, m0, m1); unpack2(mp23, m2, m3);
            *(ulonglong2*)&smh[tid][0] =
                make_ulonglong2(pack2(m0, hown.x), pack2(m1, hown.y));
            *(ulonglong2*)&smh[tid][2] =
                make_ulonglong2(pack2(m2, hown.z), pack2(m3, hown.w));
        }
        __syncthreads();

        ull azp[E4] = {0,0,0,0}, arp[E4] = {0,0,0,0}, anp[E4] = {0,0,0,0};
        #pragma unroll 4
        for (int i = 0; i < H; i++) {
            ull wzu = pack2(Wzl[i*H + j], Uzl[i*H + j]);
            ull wru = pack2(Wrl[i*H + j], Url[i*H + j]);
            ull wh0 = pack2(Whl[i*H + j], 0.f);
            ulonglong2 c01 = *(const ulonglong2*)&smh[k*H + i][0];
            ulonglong2 c23 = *(const ulonglong2*)&smh[k*H + i][2];
            azp[0] = fma2(c01.x, wzu, azp[0]);  azp[1] = fma2(c01.y, wzu, azp[1]);
            azp[2] = fma2(c23.x, wzu, azp[2]);  azp[3] = fma2(c23.y, wzu, azp[3]);
            arp[0] = fma2(c01.x, wru, arp[0]);  arp[1] = fma2(c01.y, wru, arp[1]);
            arp[2] = fma2(c23.x, wru, arp[2]);  arp[3] = fma2(c23.y, wru, arp[3]);
            anp[0] = fma2(c01.x, wh0, anp[0]);  anp[1] = fma2(c01.y, wh0, anp[1]);
            anp[2] = fma2(c23.x, wh0, anp[2]);  anp[3] = fma2(c23.y, wh0, anp[3]);
        }
        float zg[E4], rg[E4], anf[E4];
        {
            float bzv = bz[l*H + j], brv = br[l*H + j], bnv = bh[l*H + j];
            #pragma unroll
            for (int e = 0; e < E4; e++) {
                float a, b;
                unpack2(azp[e], a, b);  zg[e] = fast_sigmoid(a + b + bzv);
                unpack2(arp[e], a, b);  rg[e] = fast_sigmoid(a + b + brv);
                unpack2(anp[e], a, b);  anf[e] = a + b + bnv;
            }
        }
        srh4[tid] = make_float4(rg[0]*hown.x, rg[1]*hown.y, rg[2]*hown.z, rg[3]*hown.w);
        __syncthreads();

        #pragma unroll 4
        for (int i = 0; i < H; i++) {
            float uh = Uhl[i*H + j];
            float4 rv = srh4[k*H + i];
            anf[0] += rv.x*uh; anf[1] += rv.y*uh; anf[2] += rv.z*uh; anf[3] += rv.w*uh;
        }
        float4 h0v = sh04[tid];
        float4 hn;
        hn.x = (1.f - zg[0])*hown.x + zg[0]*fast_tanh(anf[0]) + h0v.x;
        hn.y = (1.f - zg[1])*hown.y + zg[1]*fast_tanh(anf[1]) + h0v.y;
        hn.z = (1.f - zg[2])*hown.z + zg[2]*fast_tanh(anf[2]) + h0v.z;
        hn.w = (1.f - zg[3])*hown.w + zg[3]*fast_tanh(anf[3]) + h0v.w;
        __syncthreads();
        sh4[tid] = hn;
        __syncthreads();
    }

    *(float4*)&g_comb[((size_t)t*KH + tid)*B + b0] = sh4[tid];
}

// ---------------------------------------------------------------------------
// Projection: g_proj[t][s][b][g] = comb[t][:,b] @ Wcat[:, s*G+g] + bcat
// grid (B/NBP, T), 256 threads. Coalesced weight loads AND stores.
// ---------------------------------------------------------------------------
__global__ __launch_bounds__(G, 2) void proj_kernel()
{
    __shared__ ulonglong2 scomb[KH][NBP/4];   // 20KB

    const int g  = threadIdx.x;
    const int b0 = blockIdx.x * NBP;
    const int t  = blockIdx.y;

    for (int idx = g; idx < KH*(NBP/4); idx += G) {
        int row = idx >> 2, p = idx & 3;
        scomb[row][p] = *(const ulonglong2*)&g_comb[((size_t)t*KH + row)*B + b0 + 4*p];
    }
    __syncthreads();

    ull acc[3][8];
    #pragma unroll
    for (int s = 0; s < 3; s++) {
        ull bv = pack1(g_bcat[s*G + g]);
        #pragma unroll
        for (int q = 0; q < 8; q++) acc[s][q] = bv;
    }

    const float* wbase = g_wcat + g;
    #pragma unroll 4
    for (int i = 0; i < KH; i++) {
        // coalesced: each warp reads one 128B line per (i,s)
        ull w0 = pack1(wbase[i*(3*G) + 0*G]);
        ull w1 = pack1(wbase[i*(3*G) + 1*G]);
        ull w2 = pack1(wbase[i*(3*G) + 2*G]);
        #pragma unroll
        for (int p = 0; p < 4; p++) {
            ulonglong2 c = scomb[i][p];
            acc[0][2*p]   = fma2(c.x, w0, acc[0][2*p]);
            acc[0][2*p+1] = fma2(c.y, w0, acc[0][2*p+1]);
            acc[1][2*p]   = fma2(c.x, w1, acc[1][2*p]);
            acc[1][2*p+1] = fma2(c.y, w1, acc[1][2*p+1]);
            acc[2][2*p]   = fma2(c.x, w2, acc[2][2*p]);
            acc[2][2*p+1] = fma2(c.y, w2, acc[2][2*p+1]);
        }
    }

    // stores: [t][s][b][g], g contiguous -> coalesced STG.32
    #pragma unroll
    for (int s = 0; s < 3; s++) {
        float* dst = &g_proj[(((size_t)t*3 + s)*B + b0)*G + g];
        #pragma unroll
        for (int q = 0; q < 8; q++) {
            float lo, hi;
            unpack2(acc[s][q], lo, hi);
            dst[(size_t)(2*q)*G]   = lo;
            dst[(size_t)(2*q+1)*G] = hi;
        }
    }
}

// ---------------------------------------------------------------------------
// Recurrent GARU: 128 blocks x 1024 threads, 8 batches/block.
// 4-way split-K over the 256 reduction rows. (R8 structure, proven 1.45ms;
// only the proj reads + interleaved z/r weights changed.)
// ---------------------------------------------------------------------------
__global__ __launch_bounds__(RT, 1) void recur_kernel(
    const float* __restrict__ Ugn)
{
    extern __shared__ ulonglong2 dyn2[];
    ulonglong2* sh   = dyn2;            // [col*2 + half]
    ulonglong2* srh  = sh  + 512;
    ulonglong2* sred = srh + 512;       // [((gate*4 + q)*G + col)*2 + half]

    const int tid = threadIdx.x;
    const int g   = tid & (G - 1);
    const int q   = tid >> 8;           // reduction quarter 0..3
    const int b0  = blockIdx.x * GB;
    const int i0  = q * (G/4);

    if (tid < 512) sh[tid] = make_ulonglong2(0ULL, 0ULL);
    __syncthreads();

    float zf[4], hf[4];
    ulonglong2 pn = make_ulonglong2(0ULL, 0ULL);

    for (int t = 0; t < T; t++) {
        // pass 1: partial h@Ugz, h@Ugr over this quarter's 64 rows
        ull az[4] = {0,0,0,0}, ar[4] = {0,0,0,0};
        #pragma unroll 4
        for (int i = i0; i < i0 + G/4; i++) {
            float2 w = g_uzr[i*G + g];
            ull uz2 = pack1(w.x), ur2 = pack1(w.y);
            ulonglong2 h0 = sh[i*2 + 0];
            ulonglong2 h1 = sh[i*2 + 1];
            az[0] = fma2(h0.x, uz2, az[0]);  az[1] = fma2(h0.y, uz2, az[1]);
            az[2] = fma2(h1.x, uz2, az[2]);  az[3] = fma2(h1.y, uz2, az[3]);
            ar[0] = fma2(h0.x, ur2, ar[0]);  ar[1] = fma2(h0.y, ur2, ar[1]);
            ar[2] = fma2(h1.x, ur2, ar[2]);  ar[3] = fma2(h1.y, ur2, ar[3]);
        }
        sred[((0*4 + q)*G + g)*2 + 0] = make_ulonglong2(az[0], az[1]);
        sred[((0*4 + q)*G + g)*2 + 1] = make_ulonglong2(az[2], az[3]);
        sred[((1*4 + q)*G + g)*2 + 0] = make_ulonglong2(ar[0], ar[1]);
        sred[((1*4 + q)*G + g)*2 + 1] = make_ulonglong2(ar[2], ar[3]);
        __syncthreads();

        if (tid < 512) {
            const int col = tid & (G-1), half = tid >> 8;
            ulonglong2 zp = sred[((0*4+0)*G + col)*2 + half];
            ulonglong2 rp = sred[((1*4+0)*G + col)*2 + half];
            #pragma unroll
            for (int qq = 1; qq < 4; qq++) {
                zp = add2v(zp, sred[((0*4+qq)*G + col)*2 + half]);
                rp = add2v(rp, sred[((1*4+qq)*G + col)*2 + half]);
            }
            // proj reads: [t][s][b][g], coalesced over col
            const size_t pb = (((size_t)t*3 + 0)*B + b0 + 4*half)*G + col;
            zp = add2v(zp, make_ulonglong2(
                pack2(g_proj[pb],       g_proj[pb + G]),
                pack2(g_proj[pb + 2*G], g_proj[pb + 3*G])));
            const size_t prI = pb + (size_t)B*G;
            rp = add2v(rp, make_ulonglong2(
                pack2(g_proj[prI],       g_proj[prI + G]),
                pack2(g_proj[prI + 2*G], g_proj[prI + 3*G])));
            const size_t pnI = pb + (size_t)2*B*G;
            pn = make_ulonglong2(
                pack2(g_proj[pnI],       g_proj[pnI + G]),
                pack2(g_proj[pnI + 2*G], g_proj[pnI + 3*G]));

            ulonglong2 hold = sh[col*2 + half];
            unpack2(hold.x, hf[0], hf[1]); unpack2(hold.y, hf[2], hf[3]);
            float zraw[4], rraw[4];
            unpack2(zp.x, zraw[0], zraw[1]); unpack2(zp.y, zraw[2], zraw[3]);
            unpack2(rp.x, rraw[0], rraw[1]); unpack2(rp.y, rraw[2], rraw[3]);
            float rh[4];
            #pragma unroll
            for (int e = 0; e < 4; e++) {
                zf[e] = fast_sigmoid(zraw[e]);
                rh[e] = fast_sigmoid(rraw[e]) * hf[e];
            }
            srh[col*2 + half] = make_ulonglong2(pack2(rh[0], rh[1]), pack2(rh[2], rh[3]));
        }
        __syncthreads();

        // pass 2: partial (r*h)@Ugn
        ull an[4] = {0,0,0,0};
        #pragma unroll 4
        for (int i = i0; i < i0 + G/4; i++) {
            ull un2 = pack1(Ugn[i*G + g]);
            ulonglong2 s0 = srh[i*2 + 0];
            ulonglong2 s1 = srh[i*2 + 1];
            an[0] = fma2(s0.x, un2, an[0]);  an[1] = fma2(s0.y, un2, an[1]);
            an[2] = fma2(s1.x, un2, an[2]);  an[3] = fma2(s1.y, un2, an[3]);
        }
        sred[((0*4 + q)*G + g)*2 + 0] = make_ulonglong2(an[0], an[1]);
        sred[((0*4 + q)*G + g)*2 + 1] = make_ulonglong2(an[2], an[3]);
        __syncthreads();

        if (tid < 512) {
            const int col = tid & (G-1), half = tid >> 8;
            ulonglong2 ap = sred[((0*4+0)*G + col)*2 + half];
            #pragma unroll
            for (int qq = 1; qq < 4; qq++)
                ap = add2v(ap, sred[((0*4+qq)*G + col)*2 + half]);
            ap = add2v(ap, pn);
            float af[4];
            unpack2(ap.x, af[0], af[1]); unpack2(ap.y, af[2], af[3]);
            float hn[4];
            #pragma unroll
            for (int e = 0; e < 4; e++)
                hn[e] = (1.f - zf[e]) * fast_tanh(af[e]) + zf[e] * hf[e];
            sh[col*2 + half] = make_ulonglong2(pack2(hn[0], hn[1]), pack2(hn[2], hn[3]));
        }
        __syncthreads();
    }

    if (tid < 512) {
        const int col = tid & (G-1), half = tid >> 8;
        ulonglong2 hv = sh[col*2 + half];
        float hfv[4];
        unpack2(hv.x, hfv[0], hfv[1]); unpack2(hv.y, hfv[2], hfv[3]);
        #pragma unroll
        for (int e = 0; e < 4; e++)
            g_h[(size_t)(b0 + 4*half + e)*G + col] = hfv[e];
    }
}

// ---------------------------------------------------------------------------
// Classifier
// ---------------------------------------------------------------------------
__global__ __launch_bounds__(64) void cls_kernel(
    const float* __restrict__ W1, const float* __restrict__ b1,
    const float* __restrict__ W2, const float* __restrict__ b2,
    float* __restrict__ out)
{
    __shared__ float wsum[2];
    const int b = blockIdx.x;
    const int j = threadIdx.x;

    const float* hb = g_h + (size_t)b*G;
    float acc = b1[j];
    #pragma unroll 8
    for (int i = 0; i < G; i++) acc += hb[i] * W1[i*64 + j];
    float hid = fmaxf(acc, 0.f);
    float v = hid * W2[j];
    #pragma unroll
    for (int o = 16; o > 0; o >>= 1) v += __shfl_down_sync(0xffffffffu, v, o);
    if ((j & 31) == 0) wsum[j >> 5] = v;
    __syncthreads();
    if (j == 0) out[b] = fast_sigmoid(wsum[0] + wsum[1] + b2[0]);
}

extern "C" void kernel_launch(void* const* d_in, const int* in_sizes, int n_in,
                              void* d_out, int out_size)
{
    const float* x    = (const float*)d_in[0];
    const float* adj  = (const float*)d_in[1];
    const float* W_fi = (const float*)d_in[2];
    const float* b_fi = (const float*)d_in[3];
    const float* Wz   = (const float*)d_in[4];
    const float* Uz   = (const float*)d_in[5];
    const float* bz   = (const float*)d_in[6];
    const float* Wr   = (const float*)d_in[7];
    const float* Ur   = (const float*)d_in[8];
    const float* br   = (const float*)d_in[9];
    const float* Wh   = (const float*)d_in[10];
    const float* Uh   = (const float*)d_in[11];
    const float* bh   = (const float*)d_in[12];
    const float* Wgp  = (const float*)d_in[13];
    const float* bgp  = (const float*)d_in[14];
    const float* Wgz  = (const float*)d_in[15];
    const float* Ugz  = (const float*)d_in[16];
    const float* bgz  = (const float*)d_in[17];
    const float* Wgr  = (const float*)d_in[18];
    const float* Ugr  = (const float*)d_in[19];
    const float* bgr  = (const float*)d_in[20];
    const float* Wgn  = (const float*)d_in[21];
    const float* Ugn  = (const float*)d_in[22];
    const float* bgn  = (const float*)d_in[23];
    const float* W1   = (const float*)d_in[24];
    const float* b1   = (const float*)d_in[25];
    const float* W2   = (const float*)d_in[26];
    const float* b2   = (const float*)d_in[27];
    float* out = (float*)d_out;

    const int recur_smem = (512 + 512 + 2*4*G*2) * (int)sizeof(ulonglong2);  // 81,920 B
    static int attr_done = 0;
    if (!attr_done) {
        cudaFuncSetAttribute(recur_kernel,
                             cudaFuncAttributeMaxDynamicSharedMemorySize, recur_smem);
        attr_done = 1;
    }

    prep_kernel<<<G*G/256, 256>>>(Ugz, Ugr);
    wcomb_kernel<<<dim3(KH, 3), G>>>(Wgp, bgp, Wgz, bgz, Wgr, bgr, Wgn, bgn);
    gnn_kernel<<<dim3(B/E4, T), KH>>>(x, adj, W_fi, b_fi,
                                      Wz, Uz, bz, Wr, Ur, br, Wh, Uh, bh);
    proj_kernel<<<dim3(B/NBP, T), G>>>();
    recur_kernel<<<B/GB, RT, recur_smem>>>(Ugn);
    cls_kernel<<<B, 64>>>(W1, b1, W2, b2, out);
}

// round 13
// speedup vs baseline: 1.5013x; 1.0278x over previous
#include <cuda_runtime.h>
#include <math.h>

#define T 96
#define B 1024
#define K 10
#define C 16
#define H 32
#define G 256
#define L 4
#define KH (K*H)     // 320
#define E4 4         // batch elements per GNN block
#define NBP 16       // batches per projection block
#define GB 8         // batches per recurrent block
#define RT 1024      // recurrent threads (256 cols x 4 reduction quarters)

typedef unsigned long long ull;

__device__ float g_comb[(size_t)T * KH * B];     // [t][kh][b]
__device__ float g_proj[(size_t)T * 3 * B * G];  // [t][s][b][g]  (g contiguous)
__device__ float g_h[B * G];
__device__ float g_wcat[KH * 3 * G];             // [i][s*G+j]  (coalesced over j)
__device__ float g_bcat[3 * G];
__device__ float2 g_uzr[G*G];                    // {uz, ur} at [i*G+g]
__device__ ulonglong2 g_wzr[L*H*H];              // {{wz,uz},{wr,ur}}
__device__ ull        g_whu[L*H*H];              // {wh, uh}

__device__ __forceinline__ float fast_tanh(float x) {
    float y; asm("tanh.approx.f32 %0, %1;" : "=f"(y) : "f"(x)); return y;
}
__device__ __forceinline__ float fast_sigmoid(float x) {
    return fmaf(0.5f, fast_tanh(0.5f * x), 0.5f);
}
__device__ __forceinline__ ull pack2(float a, float b) {
    ull r; asm("mov.b64 %0,{%1,%2};" : "=l"(r) : "f"(a), "f"(b)); return r;
}
__device__ __forceinline__ ull pack1(float a) { return pack2(a, a); }
__device__ __forceinline__ void unpack2(ull v, float& a, float& b) {
    asm("mov.b64 {%0,%1},%2;" : "=f"(a), "=f"(b) : "l"(v));
}
__device__ __forceinline__ ull fma2(ull a, ull b, ull c) {
    ull d; asm("fma.rn.f32x2 %0,%1,%2,%3;" : "=l"(d) : "l"(a), "l"(b), "l"(c)); return d;
}
__device__ __forceinline__ ull add2(ull a, ull b) {
    ull d; asm("add.rn.f32x2 %0,%1,%2;" : "=l"(d) : "l"(a), "l"(b)); return d;
}
__device__ __forceinline__ ulonglong2 add2v(ulonglong2 a, ulonglong2 b) {
    a.x = add2(a.x, b.x); a.y = add2(a.y, b.y); return a;
}

// ---------------------------------------------------------------------------
// prep: interleave recur z/r weights + pack gnn gate weights.
// 256 blocks x 256 threads = 65536 = G*G >= L*H*H.
// ---------------------------------------------------------------------------
__global__ __launch_bounds__(256) void prep_kernel(
    const float* __restrict__ Ugz, const float* __restrict__ Ugr,
    const float* __restrict__ Wz, const float* __restrict__ Uz,
    const float* __restrict__ Wr, const float* __restrict__ Ur,
    const float* __restrict__ Wh, const float* __restrict__ Uh)
{
    int idx = blockIdx.x * blockDim.x + threadIdx.x;
    g_uzr[idx] = make_float2(Ugz[idx], Ugr[idx]);
    if (idx < L*H*H) {
        g_wzr[idx] = make_ulonglong2(pack2(Wz[idx], Uz[idx]), pack2(Wr[idx], Ur[idx]));
        g_whu[idx] = pack2(Wh[idx], Uh[idx]);
    }
}

// ---------------------------------------------------------------------------
// Weight combine (coalesced output layout)
// ---------------------------------------------------------------------------
__global__ __launch_bounds__(G) void wcomb_kernel(
    const float* __restrict__ Wgp, const float* __restrict__ bgp,
    const float* __restrict__ Wgz, const float* __restrict__ bgz,
    const float* __restrict__ Wgr, const float* __restrict__ bgr,
    const float* __restrict__ Wgn, const float* __restrict__ bgn)
{
    __shared__ float sa[G], sb[G];
    const int i = blockIdx.x, s = blockIdx.y, j = threadIdx.x;
    const float* Ws = (s == 0) ? Wgz : (s == 1) ? Wgr : Wgn;
    const float* bs = (s == 0) ? bgz : (s == 1) ? bgr : bgn;

    sa[j] = Wgp[i*G + j];
    if (i == 0) sb[j] = bgp[j];
    __syncthreads();

    float acc = 0.f;
    #pragma unroll 8
    for (int k = 0; k < G; k++) acc += sa[k] * Ws[k*G + j];
    g_wcat[i*(3*G) + s*G + j] = acc;

    if (i == 0) {
        float bacc = bs[j];
        #pragma unroll 8
        for (int k = 0; k < G; k++) bacc += sb[k] * Ws[k*G + j];
        g_bcat[s*G + j] = bacc;
    }
}

// ---------------------------------------------------------------------------
// GNN: grid (B/E4, T), 320 threads = (k,j). 4 batch elements per block.
// Packed weights; n gate fully in second loop via smh rewrite {m,h}->{m,rh}.
// ---------------------------------------------------------------------------
__global__ __launch_bounds__(KH, 3) void gnn_kernel(
    const float* __restrict__ x, const float* __restrict__ adj,
    const float* __restrict__ W_fi, const float* __restrict__ b_fi,
    const float* __restrict__ bz, const float* __restrict__ br,
    const float* __restrict__ bh)
{
    __shared__ float      sx[E4][K*C];
    __shared__ float      sadj[E4][K*K];
    __shared__ float      sdeg[E4][K];
    __shared__ ulonglong2 sadjT[K*K];
    __shared__ float4     sh4[KH], sh04[KH];
    __shared__ ull        smh[KH][4];   // {m_e, h_e}; rewritten to {m_e, rh_e}

    const int b0  = blockIdx.x * E4;
    const int t   = blockIdx.y;
    const int tid = threadIdx.x;
    const int k   = tid >> 5;
    const int j   = tid & 31;

    for (int idx = tid; idx < E4*K*C; idx += KH) {
        int e = idx / (K*C), r = idx - e*(K*C);
        sx[e][r] = x[((size_t)t*B + b0 + e)*(K*C) + r];
    }
    for (int idx = tid; idx < E4*K*K; idx += KH) {
        int e = idx / (K*K), r = idx - e*(K*K);
        int row = r / K, col = r - row*K;
        sadj[e][r] = adj[((size_t)t*B + b0 + e)*(K*K) + r] + (row == col ? 1.f : 0.f);
    }
    __syncthreads();
    if (tid < E4*K) {
        int e = tid / K, r = tid - e*K;
        float s = 0.f;
        #pragma unroll
        for (int i = 0; i < K; i++) s += sadj[e][r*K + i];
        sdeg[e][r] = 1.f / (s + 1e-6f);
    }
    __syncthreads();
    for (int idx = tid; idx < E4*K*K; idx += KH) {
        int e = idx / (K*K), r = idx - e*(K*K);
        sadj[e][r] *= sdeg[e][r / K];
    }
    __syncthreads();
    if (tid < K*K) {
        sadjT[tid] = make_ulonglong2(pack2(sadj[0][tid], sadj[1][tid]),
                                     pack2(sadj[2][tid], sadj[3][tid]));
    }

    // h0 = x @ W_fi + b_fi
    float a0[E4];
    {
        float bv = b_fi[j];
        #pragma unroll
        for (int e = 0; e < E4; e++) a0[e] = bv;
    }
    #pragma unroll
    for (int c = 0; c < C; c++) {
        float w = W_fi[c*H + j];
        #pragma unroll
        for (int e = 0; e < E4; e++) a0[e] += sx[e][k*C + c] * w;
    }
    {
        float4 v = make_float4(a0[0], a0[1], a0[2], a0[3]);
        sh04[tid] = v;
        sh4[tid]  = v;
    }
    __syncthreads();

    for (int l = 0; l < L; l++) {
        // m = adj_norm @ h
        ull mp01 = 0ULL, mp23 = 0ULL;
        #pragma unroll
        for (int i = 0; i < K; i++) {
            ulonglong2 a2 = sadjT[k*K + i];
            ulonglong2 h2 = *(const ulonglong2*)&sh4[i*H + j];
            mp01 = fma2(a2.x, h2.x, mp01);
            mp23 = fma2(a2.y, h2.y, mp23);
        }
        float4 hown = sh4[tid];
        float m0, m1, m2, m3;
        unpack2(mp01, m0, m1); unpack2(mp23, m2, m3);
        *(ulonglong2*)&smh[tid][0] =
            make_ulonglong2(pack2(m0, hown.x), pack2(m1, hown.y));
        *(ulonglong2*)&smh[tid][2] =
            make_ulonglong2(pack2(m2, hown.z), pack2(m3, hown.w));
        __syncthreads();   // smh {m,h} published

        // gate loop: z, r only. 1 LDG.128 + 2 LDS.128 + 8 FMA2 per iter.
        ull azp[E4] = {0,0,0,0}, arp[E4] = {0,0,0,0};
        #pragma unroll 4
        for (int i = 0; i < H; i++) {
            ulonglong2 wzr = g_wzr[(l*H + i)*H + j];
            ulonglong2 c01 = *(const ulonglong2*)&smh[k*H + i][0];
            ulonglong2 c23 = *(const ulonglong2*)&smh[k*H + i][2];
            azp[0] = fma2(c01.x, wzr.x, azp[0]);  azp[1] = fma2(c01.y, wzr.x, azp[1]);
            azp[2] = fma2(c23.x, wzr.x, azp[2]);  azp[3] = fma2(c23.y, wzr.x, azp[3]);
            arp[0] = fma2(c01.x, wzr.y, arp[0]);  arp[1] = fma2(c01.y, wzr.y, arp[1]);
            arp[2] = fma2(c23.x, wzr.y, arp[2]);  arp[3] = fma2(c23.y, wzr.y, arp[3]);
        }
        float zg[E4], rg[E4];
        {
            float bzv = bz[l*H + j], brv = br[l*H + j];
            #pragma unroll
            for (int e = 0; e < E4; e++) {
                float a, b;
                unpack2(azp[e], a, b);  zg[e] = fast_sigmoid(a + b + bzv);
                unpack2(arp[e], a, b);  rg[e] = fast_sigmoid(a + b + brv);
            }
        }
        __syncthreads();   // all gate-loop smh reads complete

        // rewrite smh -> {m, r*h}
        *(ulonglong2*)&smh[tid][0] =
            make_ulonglong2(pack2(m0, rg[0]*hown.x), pack2(m1, rg[1]*hown.y));
        *(ulonglong2*)&smh[tid][2] =
            make_ulonglong2(pack2(m2, rg[2]*hown.z), pack2(m3, rg[3]*hown.w));
        __syncthreads();   // smh {m,rh} published

        // n loop: an = bn + sum {m*wh + rh*uh}. 1 LDG.64 + 2 LDS.128 + 4 FMA2.
        ull anp[E4];
        {
            float bnv = bh[l*H + j];
            ull an0 = pack2(bnv, 0.f);
            #pragma unroll
            for (int e = 0; e < E4; e++) anp[e] = an0;
        }
        #pragma unroll 4
        for (int i = 0; i < H; i++) {
            ull whu = g_whu[(l*H + i)*H + j];
            ulonglong2 c01 = *(const ulonglong2*)&smh[k*H + i][0];
            ulonglong2 c23 = *(const ulonglong2*)&smh[k*H + i][2];
            anp[0] = fma2(c01.x, whu, anp[0]);  anp[1] = fma2(c01.y, whu, anp[1]);
            anp[2] = fma2(c23.x, whu, anp[2]);  anp[3] = fma2(c23.y, whu, anp[3]);
        }
        float anf[E4];
        #pragma unroll
        for (int e = 0; e < E4; e++) {
            float a, b;
            unpack2(anp[e], a, b);
            anf[e] = a + b;
        }
        float4 h0v = sh04[tid];
        float4 hn;
        hn.x = (1.f - zg[0])*hown.x + zg[0]*fast_tanh(anf[0]) + h0v.x;
        hn.y = (1.f - zg[1])*hown.y + zg[1]*fast_tanh(anf[1]) + h0v.y;
        hn.z = (1.f - zg[2])*hown.z + zg[2]*fast_tanh(anf[2]) + h0v.z;
        hn.w = (1.f - zg[3])*hown.w + zg[3]*fast_tanh(anf[3]) + h0v.w;
        sh4[tid] = hn;   // safe: all sh4 reads of this layer ended before the
                         // smh-rewrite barrier; published by next layer's barrier
        __syncthreads();
    }

    *(float4*)&g_comb[((size_t)t*KH + tid)*B + b0] = sh4[tid];
}

// ---------------------------------------------------------------------------
// Projection (unchanged from R12 winner)
// ---------------------------------------------------------------------------
__global__ __launch_bounds__(G, 2) void proj_kernel()
{
    __shared__ ulonglong2 scomb[KH][NBP/4];   // 20KB

    const int g  = threadIdx.x;
    const int b0 = blockIdx.x * NBP;
    const int t  = blockIdx.y;

    for (int idx = g; idx < KH*(NBP/4); idx += G) {
        int row = idx >> 2, p = idx & 3;
        scomb[row][p] = *(const ulonglong2*)&g_comb[((size_t)t*KH + row)*B + b0 + 4*p];
    }
    __syncthreads();

    ull acc[3][8];
    #pragma unroll
    for (int s = 0; s < 3; s++) {
        ull bv = pack1(g_bcat[s*G + g]);
        #pragma unroll
        for (int q = 0; q < 8; q++) acc[s][q] = bv;
    }

    const float* wbase = g_wcat + g;
    #pragma unroll 4
    for (int i = 0; i < KH; i++) {
        ull w0 = pack1(wbase[i*(3*G) + 0*G]);
        ull w1 = pack1(wbase[i*(3*G) + 1*G]);
        ull w2 = pack1(wbase[i*(3*G) + 2*G]);
        #pragma unroll
        for (int p = 0; p < 4; p++) {
            ulonglong2 c = scomb[i][p];
            acc[0][2*p]   = fma2(c.x, w0, acc[0][2*p]);
            acc[0][2*p+1] = fma2(c.y, w0, acc[0][2*p+1]);
            acc[1][2*p]   = fma2(c.x, w1, acc[1][2*p]);
            acc[1][2*p+1] = fma2(c.y, w1, acc[1][2*p+1]);
            acc[2][2*p]   = fma2(c.x, w2, acc[2][2*p]);
            acc[2][2*p+1] = fma2(c.y, w2, acc[2][2*p+1]);
        }
    }

    #pragma unroll
    for (int s = 0; s < 3; s++) {
        float* dst = &g_proj[(((size_t)t*3 + s)*B + b0)*G + g];
        #pragma unroll
        for (int q = 0; q < 8; q++) {
            float lo, hi;
            unpack2(acc[s][q], lo, hi);
            dst[(size_t)(2*q)*G]   = lo;
            dst[(size_t)(2*q+1)*G] = hi;
        }
    }
}

// ---------------------------------------------------------------------------
// Recurrent GARU (unchanged from R12 winner)
// ---------------------------------------------------------------------------
__global__ __launch_bounds__(RT, 1) void recur_kernel(
    const float* __restrict__ Ugn)
{
    extern __shared__ ulonglong2 dyn2[];
    ulonglong2* sh   = dyn2;
    ulonglong2* srh  = sh  + 512;
    ulonglong2* sred = srh + 512;

    const int tid = threadIdx.x;
    const int g   = tid & (G - 1);
    const int q   = tid >> 8;
    const int b0  = blockIdx.x * GB;
    const int i0  = q * (G/4);

    if (tid < 512) sh[tid] = make_ulonglong2(0ULL, 0ULL);
    __syncthreads();

    float zf[4], hf[4];
    ulonglong2 pn = make_ulonglong2(0ULL, 0ULL);

    for (int t = 0; t < T; t++) {
        ull az[4] = {0,0,0,0}, ar[4] = {0,0,0,0};
        #pragma unroll 4
        for (int i = i0; i < i0 + G/4; i++) {
            float2 w = g_uzr[i*G + g];
            ull uz2 = pack1(w.x), ur2 = pack1(w.y);
            ulonglong2 h0 = sh[i*2 + 0];
            ulonglong2 h1 = sh[i*2 + 1];
            az[0] = fma2(h0.x, uz2, az[0]);  az[1] = fma2(h0.y, uz2, az[1]);
            az[2] = fma2(h1.x, uz2, az[2]);  az[3] = fma2(h1.y, uz2, az[3]);
            ar[0] = fma2(h0.x, ur2, ar[0]);  ar[1] = fma2(h0.y, ur2, ar[1]);
            ar[2] = fma2(h1.x, ur2, ar[2]);  ar[3] = fma2(h1.y, ur2, ar[3]);
        }
        sred[((0*4 + q)*G + g)*2 + 0] = make_ulonglong2(az[0], az[1]);
        sred[((0*4 + q)*G + g)*2 + 1] = make_ulonglong2(az[2], az[3]);
        sred[((1*4 + q)*G + g)*2 + 0] = make_ulonglong2(ar[0], ar[1]);
        sred[((1*4 + q)*G + g)*2 + 1] = make_ulonglong2(ar[2], ar[3]);
        __syncthreads();

        if (tid < 512) {
            const int col = tid & (G-1), half = tid >> 8;
            ulonglong2 zp = sred[((0*4+0)*G + col)*2 + half];
            ulonglong2 rp = sred[((1*4+0)*G + col)*2 + half];
            #pragma unroll
            for (int qq = 1; qq < 4; qq++) {
                zp = add2v(zp, sred[((0*4+qq)*G + col)*2 + half]);
                rp = add2v(rp, sred[((1*4+qq)*G + col)*2 + half]);
            }
            const size_t pb = (((size_t)t*3 + 0)*B + b0 + 4*half)*G + col;
            zp = add2v(zp, make_ulonglong2(
                pack2(g_proj[pb],       g_proj[pb + G]),
                pack2(g_proj[pb + 2*G], g_proj[pb + 3*G])));
            const size_t prI = pb + (size_t)B*G;
            rp = add2v(rp, make_ulonglong2(
                pack2(g_proj[prI],       g_proj[prI + G]),
                pack2(g_proj[prI + 2*G], g_proj[prI + 3*G])));
            const size_t pnI = pb + (size_t)2*B*G;
            pn = make_ulonglong2(
                pack2(g_proj[pnI],       g_proj[pnI + G]),
                pack2(g_proj[pnI + 2*G], g_proj[pnI + 3*G]));

            ulonglong2 hold = sh[col*2 + half];
            unpack2(hold.x, hf[0], hf[1]); unpack2(hold.y, hf[2], hf[3]);
            float zraw[4], rraw[4];
            unpack2(zp.x, zraw[0], zraw[1]); unpack2(zp.y, zraw[2], zraw[3]);
            unpack2(rp.x, rraw[0], rraw[1]); unpack2(rp.y, rraw[2], rraw[3]);
            float rh[4];
            #pragma unroll
            for (int e = 0; e < 4; e++) {
                zf[e] = fast_sigmoid(zraw[e]);
                rh[e] = fast_sigmoid(rraw[e]) * hf[e];
            }
            srh[col*2 + half] = make_ulonglong2(pack2(rh[0], rh[1]), pack2(rh[2], rh[3]));
        }
        __syncthreads();

        ull an[4] = {0,0,0,0};
        #pragma unroll 4
        for (int i = i0; i < i0 + G/4; i++) {
            ull un2 = pack1(Ugn[i*G + g]);
            ulonglong2 s0 = srh[i*2 + 0];
            ulonglong2 s1 = srh[i*2 + 1];
            an[0] = fma2(s0.x, un2, an[0]);  an[1] = fma2(s0.y, un2, an[1]);
            an[2] = fma2(s1.x, un2, an[2]);  an[3] = fma2(s1.y, un2, an[3]);
        }
        sred[((0*4 + q)*G + g)*2 + 0] = make_ulonglong2(an[0], an[1]);
        sred[((0*4 + q)*G + g)*2 + 1] = make_ulonglong2(an[2], an[3]);
        __syncthreads();

        if (tid < 512) {
            const int col = tid & (G-1), half = tid >> 8;
            ulonglong2 ap = sred[((0*4+0)*G + col)*2 + half];
            #pragma unroll
            for (int qq = 1; qq < 4; qq++)
                ap = add2v(ap, sred[((0*4+qq)*G + col)*2 + half]);
            ap = add2v(ap, pn);
            float af[4];
            unpack2(ap.x, af[0], af[1]); unpack2(ap.y, af[2], af[3]);
            float hn[4];
            #pragma unroll
            for (int e = 0; e < 4; e++)
                hn[e] = (1.f - zf[e]) * fast_tanh(af[e]) + zf[e] * hf[e];
            sh[col*2 + half] = make_ulonglong2(pack2(hn[0], hn[1]), pack2(hn[2], hn[3]));
        }
        __syncthreads();
    }

    if (tid < 512) {
        const int col = tid & (G-1), half = tid >> 8;
        ulonglong2 hv = sh[col*2 + half];
        float hfv[4];
        unpack2(hv.x, hfv[0], hfv[1]); unpack2(hv.y, hfv[2], hfv[3]);
        #pragma unroll
        for (int e = 0; e < 4; e++)
            g_h[(size_t)(b0 + 4*half + e)*G + col] = hfv[e];
    }
}

// ---------------------------------------------------------------------------
// Classifier (unchanged)
// ---------------------------------------------------------------------------
__global__ __launch_bounds__(64) void cls_kernel(
    const float* __restrict__ W1, const float* __restrict__ b1,
    const float* __restrict__ W2, const float* __restrict__ b2,
    float* __restrict__ out)
{
    __shared__ float wsum[2];
    const int b = blockIdx.x;
    const int j = threadIdx.x;

    const float* hb = g_h + (size_t)b*G;
    float acc = b1[j];
    #pragma unroll 8
    for (int i = 0; i < G; i++) acc += hb[i] * W1[i*64 + j];
    float hid = fmaxf(acc, 0.f);
    float v = hid * W2[j];
    #pragma unroll
    for (int o = 16; o > 0; o >>= 1) v += __shfl_down_sync(0xffffffffu, v, o);
    if ((j & 31) == 0) wsum[j >> 5] = v;
    __syncthreads();
    if (j == 0) out[b] = fast_sigmoid(wsum[0] + wsum[1] + b2[0]);
}

extern "C" void kernel_launch(void* const* d_in, const int* in_sizes, int n_in,
                              void* d_out, int out_size)
{
    const float* x    = (const float*)d_in[0];
    const float* adj  = (const float*)d_in[1];
    const float* W_fi = (const float*)d_in[2];
    const float* b_fi = (const float*)d_in[3];
    const float* Wz   = (const float*)d_in[4];
    const float* Uz   = (const float*)d_in[5];
    const float* bz   = (const float*)d_in[6];
    const float* Wr   = (const float*)d_in[7];
    const float* Ur   = (const float*)d_in[8];
    const float* br   = (const float*)d_in[9];
    const float* Wh   = (const float*)d_in[10];
    const float* Uh   = (const float*)d_in[11];
    const float* bh   = (const float*)d_in[12];
    const float* Wgp  = (const float*)d_in[13];
    const float* bgp  = (const float*)d_in[14];
    const float* Wgz  = (const float*)d_in[15];
    const float* Ugz  = (const float*)d_in[16];
    const float* bgz  = (const float*)d_in[17];
    const float* Wgr  = (const float*)d_in[18];
    const float* Ugr  = (const float*)d_in[19];
    const float* bgr  = (const float*)d_in[20];
    const float* Wgn  = (const float*)d_in[21];
    const float* Ugn  = (const float*)d_in[22];
    const float* bgn  = (const float*)d_in[23];
    const float* W1   = (const float*)d_in[24];
    const float* b1   = (const float*)d_in[25];
    const float* W2   = (const float*)d_in[26];
    const float* b2   = (const float*)d_in[27];
    float* out = (float*)d_out;

    const int recur_smem = (512 + 512 + 2*4*G*2) * (int)sizeof(ulonglong2);  // 81,920 B
    static int attr_done = 0;
    if (!attr_done) {
        cudaFuncSetAttribute(recur_kernel,
                             cudaFuncAttributeMaxDynamicSharedMemorySize, recur_smem);
        attr_done = 1;
    }

    prep_kernel<<<G*G/256, 256>>>(Ugz, Ugr, Wz, Uz, Wr, Ur, Wh, Uh);
    wcomb_kernel<<<dim3(KH, 3), G>>>(Wgp, bgp, Wgz, bgz, Wgr, bgr, Wgn, bgn);
    gnn_kernel<<<dim3(B/E4, T), KH>>>(x, adj, W_fi, b_fi, bz, br, bh);
    proj_kernel<<<dim3(B/NBP, T), G>>>();
    recur_kernel<<<B/GB, RT, recur_smem>>>(Ugn);
    cls_kernel<<<B, 64>>>(W1, b1, W2, b2, out);
}